// round 2
// baseline (speedup 1.0000x reference)
#include <cuda_runtime.h>
#include <cstdint>

#define BATCH 8
#define NPIX (1 << 20)
#define HARD_IND 524288u
#define PSOFT (104857.0 / 1048576.0)
#define TOTAL_ELEMS 25165824.0
#define CAP (1u << 18)          // 256K-element compact buffer per batch (expect ~70K)

// ---------------- scratch (static device memory; no allocations) ----------------
__device__ float    g_res[BATCH * NPIX];      // 32 MB: per-pixel channel-summed |x-y|
__device__ unsigned g_hist1[BATCH][4096];     // level-1 histogram (float bits >> 20)
__device__ float    g_cmp[BATCH][CAP];        // compacted candidate-bin elements
__device__ unsigned g_cmpCnt[BATCH];
__device__ double   g_sumAll[BATCH];
__device__ double   g_hardHigh[BATCH];        // sum of res in bins strictly above candidate
__device__ int      g_cand[BATCH];
__device__ unsigned g_above[BATCH];           // count strictly above candidate bin
__device__ double   g_total;

// ---------------- K0: zero small scratch ----------------
__global__ void k_zero() {
    unsigned idx = blockIdx.x * blockDim.x + threadIdx.x;
    uint4 z = make_uint4(0, 0, 0, 0);
    const unsigned n1 = (BATCH * 4096) / 4;   // 8192
    if (idx < n1) reinterpret_cast<uint4*>(&g_hist1[0][0])[idx] = z;
    if (idx < BATCH) {
        g_sumAll[idx] = 0.0; g_hardHigh[idx] = 0.0; g_cmpCnt[idx] = 0u;
    }
    if (idx == 0) g_total = 0.0;
}

// ---------------- K1: res = sum_c |x-y|, level-1 histogram, total sum ----------------
__global__ void __launch_bounds__(256) k_res(const float* __restrict__ x,
                                             const float* __restrict__ y) {
    __shared__ unsigned sh[4096];
    for (int i = threadIdx.x; i < 4096; i += 256) sh[i] = 0;
    __syncthreads();

    const int blocksPerBatch = NPIX / 4096;   // 256
    int b   = blockIdx.x / blocksPerBatch;
    int blk = blockIdx.x % blocksPerBatch;
    const float* xb = x + (size_t)b * 3 * NPIX;
    const float* yb = y + (size_t)b * 3 * NPIX;
    float* rb = g_res + (size_t)b * NPIX;
    int pix0 = blk * 4096;
    int lane = threadIdx.x & 31;
    double lsum = 0.0;

#pragma unroll
    for (int it = 0; it < 4; ++it) {
        int i = pix0 + it * 1024 + threadIdx.x * 4;
        float4 a0 = *(const float4*)(xb + i);
        float4 b0 = *(const float4*)(yb + i);
        float4 a1 = *(const float4*)(xb + NPIX + i);
        float4 b1 = *(const float4*)(yb + NPIX + i);
        float4 a2 = *(const float4*)(xb + 2 * NPIX + i);
        float4 b2 = *(const float4*)(yb + 2 * NPIX + i);
        float4 r;
        r.x = (fabsf(a0.x - b0.x) + fabsf(a1.x - b1.x)) + fabsf(a2.x - b2.x);
        r.y = (fabsf(a0.y - b0.y) + fabsf(a1.y - b1.y)) + fabsf(a2.y - b2.y);
        r.z = (fabsf(a0.z - b0.z) + fabsf(a1.z - b1.z)) + fabsf(a2.z - b2.z);
        r.w = (fabsf(a0.w - b0.w) + fabsf(a1.w - b1.w)) + fabsf(a2.w - b2.w);
        *(float4*)(rb + i) = r;
        // warp-aggregated shared histogram (hot bins -> heavy same-address conflicts otherwise)
        float vv[4] = {r.x, r.y, r.z, r.w};
#pragma unroll
        for (int k = 0; k < 4; ++k) {
            unsigned bin = __float_as_uint(vv[k]) >> 20;
            unsigned mm = __match_any_sync(0xffffffffu, bin);
            if ((mm & ((1u << lane) - 1u)) == 0)   // lowest lane with this bin
                atomicAdd(&sh[bin], (unsigned)__popc(mm));
        }
        float fs = ((vv[0] + vv[1]) + (vv[2] + vv[3]));
        lsum += (double)fs;
    }

    // block-reduce lsum
    for (int o = 16; o; o >>= 1) lsum += __shfl_down_sync(0xffffffffu, lsum, o);
    __shared__ double wsum[8];
    int w = threadIdx.x >> 5;
    if (!lane) wsum[w] = lsum;
    __syncthreads();
    if (threadIdx.x == 0) {
        double s = 0.0;
        for (int i = 0; i < 8; ++i) s += wsum[i];
        atomicAdd(&g_sumAll[b], s);
    }
    for (int i = threadIdx.x; i < 4096; i += 256) {
        unsigned c = sh[i];
        if (c) atomicAdd(&g_hist1[b][i], c);
    }
}

// ---------------- K2: find candidate level-1 bin (rank HARD_IND, descending) ------
__global__ void __launch_bounds__(1024) k_sel1() {
    int b = blockIdx.x, tid = threadIdx.x, lane = tid & 31, w = tid >> 5;
    __shared__ unsigned sh[4096];
    for (int i = tid; i < 4096; i += 1024) sh[i] = g_hist1[b][i];
    __syncthreads();
    unsigned v = sh[4 * tid] + sh[4 * tid + 1] + sh[4 * tid + 2] + sh[4 * tid + 3];
    unsigned s = v;
    for (int o = 1; o < 32; o <<= 1) {
        unsigned t = __shfl_down_sync(0xffffffffu, s, o);
        if (lane + o < 32) s += t;
    }
    __shared__ unsigned wtot[32];
    if (!lane) wtot[w] = s;
    __syncthreads();
    unsigned above = 0;
    for (int u = w + 1; u < 32; ++u) above += wtot[u];
    unsigned suffExcl = above + s - v;
    if (suffExcl <= HARD_IND && HARD_IND < suffExcl + v) {
        unsigned cum = suffExcl;
        for (int j = 3; j >= 0; --j) {
            unsigned c = sh[4 * tid + j];
            if (cum + c > HARD_IND) { g_cand[b] = 4 * tid + j; g_above[b] = cum; break; }
            cum += c;
        }
    }
}

// ---------------- K3: hard-high sum + compact candidate-bin elements ----------------
__global__ void __launch_bounds__(256) k_refine() {
    const int blocksPerBatch = NPIX / 4096;
    int b   = blockIdx.x / blocksPerBatch;
    int blk = blockIdx.x % blocksPerBatch;
    unsigned cand = (unsigned)g_cand[b];
    const float* rb = g_res + (size_t)b * NPIX;
    int pix0 = blk * 4096;
    int lane = threadIdx.x & 31;
    float* cb = g_cmp[b];
    double lhigh = 0.0;

#pragma unroll
    for (int it = 0; it < 4; ++it) {
        int i = pix0 + it * 1024 + threadIdx.x * 4;
        float4 r = *(const float4*)(rb + i);
        float vv[4] = {r.x, r.y, r.z, r.w};
        float fh = 0.0f;
#pragma unroll
        for (int k = 0; k < 4; ++k) {
            unsigned bin = __float_as_uint(vv[k]) >> 20;
            if (bin > cand) fh += vv[k];
            // warp-aggregated compaction for bin == cand
            bool pred = (bin == cand);
            unsigned m = __ballot_sync(0xffffffffu, pred);
            if (m) {
                int leader = __ffs(m) - 1;
                unsigned pos0 = 0;
                if (lane == leader) pos0 = atomicAdd(&g_cmpCnt[b], (unsigned)__popc(m));
                pos0 = __shfl_sync(0xffffffffu, pos0, leader);
                if (pred) {
                    unsigned pos = pos0 + (unsigned)__popc(m & ((1u << lane) - 1u));
                    if (pos < CAP) cb[pos] = vv[k];
                }
            }
        }
        lhigh += (double)fh;
    }
    for (int o = 16; o; o >>= 1) lhigh += __shfl_down_sync(0xffffffffu, lhigh, o);
    __shared__ double wsum[8];
    int w = threadIdx.x >> 5;
    if (!lane) wsum[w] = lhigh;
    __syncthreads();
    if (!threadIdx.x) {
        double s = 0.0;
        for (int i = 0; i < 8; ++i) s += wsum[i];
        atomicAdd(&g_hardHigh[b], s);
    }
}

// ---------------- helper: count strictly above tid (descending suffix, 1024 thr) ---
__device__ __forceinline__ unsigned suff_excl(unsigned v, int tid, unsigned* wtot) {
    int lane = tid & 31, w = tid >> 5;
    unsigned s = v;
    for (int o = 1; o < 32; o <<= 1) {
        unsigned t = __shfl_down_sync(0xffffffffu, s, o);
        if (lane + o < 32) s += t;
    }
    __syncthreads();           // protect wtot reuse
    if (!lane) wtot[w] = s;
    __syncthreads();
    unsigned above = 0;
    for (int u = w + 1; u < 32; ++u) above += wtot[u];
    return above + s - v;
}

// ---------------- K4: exact threshold + per-batch result (1 block / batch) --------
__global__ void __launch_bounds__(1024) k_final() {
    int b = blockIdx.x, tid = threadIdx.x, lane = tid & 31, w = tid >> 5;
    __shared__ unsigned cnt1[1024];
    __shared__ double   sum1[1024];
    __shared__ unsigned wtot[32];
    __shared__ double   wshd[32];
    __shared__ int sC2, sJ;
    __shared__ unsigned sRin2;
    __shared__ double sSumAbove;

    cnt1[tid] = 0; sum1[tid] = 0.0;
    __syncthreads();

    unsigned n = g_cmpCnt[b]; if (n > CAP) n = CAP;
    const float* buf = g_cmp[b];

    // pass A: bits 10..19 — count + value sum
    for (unsigned i = tid; i < n; i += 1024) {
        float v = buf[i];
        unsigned sb = (__float_as_uint(v) >> 10) & 1023u;
        atomicAdd(&cnt1[sb], 1u);
        atomicAdd(&sum1[sb], (double)v);
    }
    __syncthreads();

    unsigned v = cnt1[tid];
    unsigned se = suff_excl(v, tid, wtot);
    unsigned rin = HARD_IND - g_above[b];
    if (se <= rin && rin < se + v) { sC2 = tid; sRin2 = rin - se; }
    __syncthreads();
    int c2 = sC2;

    // parallel sum of sub-bin values strictly above c2
    double sa = (tid > c2) ? sum1[tid] : 0.0;
    for (int o = 16; o; o >>= 1) sa += __shfl_down_sync(0xffffffffu, sa, o);
    if (!lane) wshd[w] = sa;
    __syncthreads();
    if (tid == 0) {
        double s = 0.0;
        for (int i = 0; i < 32; ++i) s += wshd[i];
        sSumAbove = s;
    }
    __syncthreads();

    // pass B: bits 0..9 counts within sub-bin c2
    cnt1[tid] = 0;
    __syncthreads();
    for (unsigned i = tid; i < n; i += 1024) {
        unsigned bits = __float_as_uint(buf[i]);
        if (((bits >> 10) & 1023u) == (unsigned)c2)
            atomicAdd(&cnt1[bits & 1023u], 1u);
    }
    __syncthreads();

    v = cnt1[tid];
    se = suff_excl(v, tid, wtot);
    unsigned rin2 = sRin2;
    if (se <= rin2 && rin2 < se + v) sJ = tid;
    __syncthreads();
    int jst = sJ;

    unsigned baseb = ((unsigned)g_cand[b] << 20) | ((unsigned)c2 << 10);
    double pv = (tid > jst)
        ? (double)cnt1[tid] * (double)__uint_as_float(baseb | (unsigned)tid) : 0.0;
    for (int o = 16; o; o >>= 1) pv += __shfl_down_sync(0xffffffffu, pv, o);
    if (!lane) wshd[w] = pv;
    __syncthreads();
    if (tid == 0) {
        double s = 0.0;
        for (int i = 0; i < 32; ++i) s += wshd[i];
        double hardSum = g_hardHigh[b] + sSumAbove + s;   // exact sum of res > thre
        double result  = hardSum + PSOFT * (g_sumAll[b] - hardSum);
        atomicAdd(&g_total, result);
    }
}

// ---------------- K5: final scalar ----------------
__global__ void k_out(float* out) {
    out[0] = (float)(g_total / TOTAL_ELEMS);
}

extern "C" void kernel_launch(void* const* d_in, const int* in_sizes, int n_in,
                              void* d_out, int out_size) {
    const float* x = (const float*)d_in[0];
    const float* y = (const float*)d_in[1];
    float* out = (float*)d_out;
    k_zero  <<<64, 256>>>();
    k_res   <<<2048, 256>>>(x, y);
    k_sel1  <<<BATCH, 1024>>>();
    k_refine<<<2048, 256>>>();
    k_final <<<BATCH, 1024>>>();
    k_out   <<<1, 1>>>(out);
}

// round 4
// speedup vs baseline: 3.9147x; 3.9147x over previous
#include <cuda_runtime.h>
#include <cstdint>

#define BATCH 8
#define NPIX (1 << 20)
#define HARD_IND 524288u
#define PSOFT (104857.0 / 1048576.0)
#define TOTAL_ELEMS 25165824.0
#define CAP (1u << 18)          // global compact buffer per batch (expect ~70K used)
#define BCAP 512                // per-block smem compact capacity (expect ~280)

// ---------------- scratch (static device memory; no allocations) ----------------
__device__ float    g_res[BATCH * NPIX];      // 32 MB
__device__ unsigned g_hist1[BATCH][4096];
__device__ float    g_cmp[BATCH][CAP];
__device__ unsigned g_cmpCnt[BATCH];
__device__ double   g_sumAll[BATCH];
__device__ double   g_hardHigh[BATCH];
__device__ int      g_cand[BATCH];
__device__ unsigned g_above[BATCH];
__device__ double   g_total;

// ---------------- K0: zero small scratch ----------------
__global__ void k_zero() {
    unsigned idx = blockIdx.x * blockDim.x + threadIdx.x;
    uint4 z = make_uint4(0, 0, 0, 0);
    const unsigned n1 = (BATCH * 4096) / 4;   // 8192
    if (idx < n1) reinterpret_cast<uint4*>(&g_hist1[0][0])[idx] = z;
    if (idx < BATCH) {
        g_sumAll[idx] = 0.0; g_hardHigh[idx] = 0.0; g_cmpCnt[idx] = 0u;
    }
    if (idx == 0) g_total = 0.0;
}

// ---------------- K1: res = sum_c |x-y|, level-1 histogram, total sum -------------
// All hot-loop math in fp32; fp64 only for 8 values per block.
__global__ void __launch_bounds__(256) k_res(const float* __restrict__ x,
                                             const float* __restrict__ y) {
    __shared__ unsigned sh[4096];
    for (int i = threadIdx.x; i < 4096; i += 256) sh[i] = 0;
    __syncthreads();

    const int blocksPerBatch = NPIX / 4096;   // 256
    int b   = blockIdx.x / blocksPerBatch;
    int blk = blockIdx.x % blocksPerBatch;
    const float* xb = x + (size_t)b * 3 * NPIX;
    const float* yb = y + (size_t)b * 3 * NPIX;
    float* rb = g_res + (size_t)b * NPIX;
    int pix0 = blk * 4096;
    int lane = threadIdx.x & 31;
    float lsum = 0.0f;

#pragma unroll
    for (int it = 0; it < 4; ++it) {
        int i = pix0 + it * 1024 + threadIdx.x * 4;
        float4 a0 = *(const float4*)(xb + i);
        float4 b0 = *(const float4*)(yb + i);
        float4 a1 = *(const float4*)(xb + NPIX + i);
        float4 b1 = *(const float4*)(yb + NPIX + i);
        float4 a2 = *(const float4*)(xb + 2 * NPIX + i);
        float4 b2 = *(const float4*)(yb + 2 * NPIX + i);
        float4 r;
        r.x = (fabsf(a0.x - b0.x) + fabsf(a1.x - b1.x)) + fabsf(a2.x - b2.x);
        r.y = (fabsf(a0.y - b0.y) + fabsf(a1.y - b1.y)) + fabsf(a2.y - b2.y);
        r.z = (fabsf(a0.z - b0.z) + fabsf(a1.z - b1.z)) + fabsf(a2.z - b2.z);
        r.w = (fabsf(a0.w - b0.w) + fabsf(a1.w - b1.w)) + fabsf(a2.w - b2.w);
        *(float4*)(rb + i) = r;
        float vv[4] = {r.x, r.y, r.z, r.w};
#pragma unroll
        for (int k = 0; k < 4; ++k) {
            unsigned bin = __float_as_uint(vv[k]) >> 20;
            unsigned mm = __match_any_sync(0xffffffffu, bin);
            if ((mm & ((1u << lane) - 1u)) == 0)
                atomicAdd(&sh[bin], (unsigned)__popc(mm));
        }
        lsum += ((vv[0] + vv[1]) + (vv[2] + vv[3]));
    }

    // fp32 warp reduce, then double across 8 warps
    for (int o = 16; o; o >>= 1) lsum += __shfl_down_sync(0xffffffffu, lsum, o);
    __shared__ double wsum[8];
    int w = threadIdx.x >> 5;
    if (!lane) wsum[w] = (double)lsum;
    __syncthreads();
    if (threadIdx.x == 0) {
        double s = 0.0;
        for (int i = 0; i < 8; ++i) s += wsum[i];
        atomicAdd(&g_sumAll[b], s);
    }
    for (int i = threadIdx.x; i < 4096; i += 256) {
        unsigned c = sh[i];
        if (c) atomicAdd(&g_hist1[b][i], c);
    }
}

// ---------------- K2: candidate level-1 bin (rank HARD_IND, descending) -----------
__global__ void __launch_bounds__(1024) k_sel1() {
    int b = blockIdx.x, tid = threadIdx.x, lane = tid & 31, w = tid >> 5;
    __shared__ unsigned sh[4096];
    for (int i = tid; i < 4096; i += 1024) sh[i] = g_hist1[b][i];
    __syncthreads();
    unsigned v = sh[4 * tid] + sh[4 * tid + 1] + sh[4 * tid + 2] + sh[4 * tid + 3];
    unsigned s = v;
    for (int o = 1; o < 32; o <<= 1) {
        unsigned t = __shfl_down_sync(0xffffffffu, s, o);
        if (lane + o < 32) s += t;
    }
    __shared__ unsigned wtot[32];
    if (!lane) wtot[w] = s;
    __syncthreads();
    unsigned above = 0;
    for (int u = w + 1; u < 32; ++u) above += wtot[u];
    unsigned suffExcl = above + s - v;
    if (suffExcl <= HARD_IND && HARD_IND < suffExcl + v) {
        unsigned cum = suffExcl;
        for (int j = 3; j >= 0; --j) {
            unsigned c = sh[4 * tid + j];
            if (cum + c > HARD_IND) { g_cand[b] = 4 * tid + j; g_above[b] = cum; break; }
            cum += c;
        }
    }
}

// ---------------- K3: hard-high sum + block-local compaction ----------------------
__global__ void __launch_bounds__(256) k_refine() {
    const int blocksPerBatch = NPIX / 4096;
    int b   = blockIdx.x / blocksPerBatch;
    int blk = blockIdx.x % blocksPerBatch;
    unsigned cand = (unsigned)g_cand[b];
    const float* rb = g_res + (size_t)b * NPIX;
    int pix0 = blk * 4096;
    int lane = threadIdx.x & 31;

    __shared__ float sbuf[BCAP];
    __shared__ unsigned scnt, sbase;
    __shared__ double wsum[8];
    if (threadIdx.x == 0) scnt = 0;
    __syncthreads();

    float fh = 0.0f;
#pragma unroll
    for (int it = 0; it < 4; ++it) {
        int i = pix0 + it * 1024 + threadIdx.x * 4;
        float4 r = *(const float4*)(rb + i);
        float vv[4] = {r.x, r.y, r.z, r.w};
#pragma unroll
        for (int k = 0; k < 4; ++k) {
            unsigned bin = __float_as_uint(vv[k]) >> 20;
            if (bin > cand) fh += vv[k];
            else if (bin == cand) {
                unsigned idx = atomicAdd(&scnt, 1u);
                if (idx < BCAP) sbuf[idx] = vv[k];
            }
        }
    }
    for (int o = 16; o; o >>= 1) fh += __shfl_down_sync(0xffffffffu, fh, o);
    int w = threadIdx.x >> 5;
    if (!lane) wsum[w] = (double)fh;
    __syncthreads();
    if (threadIdx.x == 0) {
        double s = 0.0;
        for (int i = 0; i < 8; ++i) s += wsum[i];
        atomicAdd(&g_hardHigh[b], s);
        unsigned c = scnt; if (c > BCAP) c = BCAP;
        sbase = atomicAdd(&g_cmpCnt[b], c);   // ONE global atomic per block
        scnt = c;
    }
    __syncthreads();
    float* cb = g_cmp[b];
    unsigned c = scnt, base = sbase;
    for (unsigned i = threadIdx.x; i < c; i += 256) {
        unsigned pos = base + i;
        if (pos < CAP) cb[pos] = sbuf[i];
    }
}

// ---------------- helper: count strictly above tid (descending suffix) ------------
__device__ __forceinline__ unsigned suff_excl(unsigned v, int tid, unsigned* wtot) {
    int lane = tid & 31, w = tid >> 5;
    unsigned s = v;
    for (int o = 1; o < 32; o <<= 1) {
        unsigned t = __shfl_down_sync(0xffffffffu, s, o);
        if (lane + o < 32) s += t;
    }
    __syncthreads();
    if (!lane) wtot[w] = s;
    __syncthreads();
    unsigned above = 0;
    for (int u = w + 1; u < 32; ++u) above += wtot[u];
    return above + s - v;
}

// ---------------- K4: exact threshold + per-batch result (1 block / batch) --------
__global__ void __launch_bounds__(1024) k_final() {
    int b = blockIdx.x, tid = threadIdx.x, lane = tid & 31, w = tid >> 5;
    __shared__ unsigned cnt1[1024];
    __shared__ float    sum1[1024];
    __shared__ unsigned wtot[32];
    __shared__ double   wshd[32];
    __shared__ int sC2, sJ;
    __shared__ unsigned sRin2;
    __shared__ double sSumAbove;

    cnt1[tid] = 0; sum1[tid] = 0.0f;
    __syncthreads();

    unsigned n = g_cmpCnt[b]; if (n > CAP) n = CAP;
    const float* buf = g_cmp[b];

    // pass A: bits 10..19 — count + fp32 value sum
    for (unsigned i = tid; i < n; i += 1024) {
        float v = buf[i];
        unsigned sb = (__float_as_uint(v) >> 10) & 1023u;
        atomicAdd(&cnt1[sb], 1u);
        atomicAdd(&sum1[sb], v);
    }
    __syncthreads();

    unsigned v = cnt1[tid];
    unsigned se = suff_excl(v, tid, wtot);
    unsigned rin = HARD_IND - g_above[b];
    if (se <= rin && rin < se + v) { sC2 = tid; sRin2 = rin - se; }
    __syncthreads();
    int c2 = sC2;

    double sa = (tid > c2) ? (double)sum1[tid] : 0.0;
    for (int o = 16; o; o >>= 1) sa += __shfl_down_sync(0xffffffffu, sa, o);
    if (!lane) wshd[w] = sa;
    __syncthreads();
    if (tid == 0) {
        double s = 0.0;
        for (int i = 0; i < 32; ++i) s += wshd[i];
        sSumAbove = s;
    }
    __syncthreads();

    // pass B: bits 0..9 counts within sub-bin c2
    cnt1[tid] = 0;
    __syncthreads();
    for (unsigned i = tid; i < n; i += 1024) {
        unsigned bits = __float_as_uint(buf[i]);
        if (((bits >> 10) & 1023u) == (unsigned)c2)
            atomicAdd(&cnt1[bits & 1023u], 1u);
    }
    __syncthreads();

    v = cnt1[tid];
    se = suff_excl(v, tid, wtot);
    unsigned rin2 = sRin2;
    if (se <= rin2 && rin2 < se + v) sJ = tid;
    __syncthreads();
    int jst = sJ;

    unsigned baseb = ((unsigned)g_cand[b] << 20) | ((unsigned)c2 << 10);
    double pv = (tid > jst)
        ? (double)cnt1[tid] * (double)__uint_as_float(baseb | (unsigned)tid) : 0.0;
    for (int o = 16; o; o >>= 1) pv += __shfl_down_sync(0xffffffffu, pv, o);
    if (!lane) wshd[w] = pv;
    __syncthreads();
    if (tid == 0) {
        double s = 0.0;
        for (int i = 0; i < 32; ++i) s += wshd[i];
        double hardSum = g_hardHigh[b] + sSumAbove + s;   // exact sum of res > thre
        double result  = hardSum + PSOFT * (g_sumAll[b] - hardSum);
        atomicAdd(&g_total, result);
    }
}

// ---------------- K5: final scalar ----------------
__global__ void k_out(float* out) {
    out[0] = (float)(g_total / TOTAL_ELEMS);
}

extern "C" void kernel_launch(void* const* d_in, const int* in_sizes, int n_in,
                              void* d_out, int out_size) {
    const float* x = (const float*)d_in[0];
    const float* y = (const float*)d_in[1];
    float* out = (float*)d_out;
    k_zero  <<<64, 256>>>();
    k_res   <<<2048, 256>>>(x, y);
    k_sel1  <<<BATCH, 1024>>>();
    k_refine<<<2048, 256>>>();
    k_final <<<BATCH, 1024>>>();
    k_out   <<<1, 1>>>(out);
}

// round 5
// speedup vs baseline: 3.9775x; 1.0161x over previous
#include <cuda_runtime.h>
#include <cstdint>

#define BATCH 8
#define NPIX (1 << 20)
#define HARD_IND 524288u
#define PSOFT (104857.0 / 1048576.0)
#define TOTAL_ELEMS 25165824.0
#define CAP (1u << 18)          // global compact buffer per batch (expect ~70K used)
#define BCAP 512                // per-block smem compact capacity (expect ~280)

// ---------------- scratch (static device memory; zero-initialized at load) -------
// INVARIANT: every kernel that consumes a cross-run accumulator resets it to 0
// after use, so each pipeline run starts from a clean state (graph replays).
__device__ float    g_res[BATCH * NPIX];      // 32 MB (fully rewritten each run)
__device__ unsigned g_hist1[BATCH][4096];     // zeroed by k_sel1 after reading
__device__ float    g_cmp[BATCH][CAP];        // data region, bounded by g_cmpCnt
__device__ unsigned g_cmpCnt[BATCH];          // zeroed by k_final after reading
__device__ double   g_sumAll[BATCH];          // zeroed by k_final after reading
__device__ double   g_hardHigh[BATCH];        // zeroed by k_final after reading
__device__ int      g_cand[BATCH];            // overwritten each run
__device__ unsigned g_above[BATCH];           // overwritten each run
__device__ double   g_total;                  // zeroed by k_out after reading

// ---------------- K1: res = sum_c |x-y| + level-1 histogram (lean hot loop) ------
__global__ void __launch_bounds__(256) k_res(const float* __restrict__ x,
                                             const float* __restrict__ y) {
    __shared__ unsigned sh[4096];
    for (int i = threadIdx.x; i < 4096; i += 256) sh[i] = 0;
    __syncthreads();

    const int blocksPerBatch = NPIX / 4096;   // 256
    int b   = blockIdx.x / blocksPerBatch;
    int blk = blockIdx.x % blocksPerBatch;
    const float* xb = x + (size_t)b * 3 * NPIX;
    const float* yb = y + (size_t)b * 3 * NPIX;
    float* rb = g_res + (size_t)b * NPIX;
    int pix0 = blk * 4096;

#pragma unroll
    for (int it = 0; it < 4; ++it) {
        int i = pix0 + it * 1024 + threadIdx.x * 4;
        float4 a0 = *(const float4*)(xb + i);
        float4 b0 = *(const float4*)(yb + i);
        float4 a1 = *(const float4*)(xb + NPIX + i);
        float4 b1 = *(const float4*)(yb + NPIX + i);
        float4 a2 = *(const float4*)(xb + 2 * NPIX + i);
        float4 b2 = *(const float4*)(yb + 2 * NPIX + i);
        float4 r;
        r.x = (fabsf(a0.x - b0.x) + fabsf(a1.x - b1.x)) + fabsf(a2.x - b2.x);
        r.y = (fabsf(a0.y - b0.y) + fabsf(a1.y - b1.y)) + fabsf(a2.y - b2.y);
        r.z = (fabsf(a0.z - b0.z) + fabsf(a1.z - b1.z)) + fabsf(a2.z - b2.z);
        r.w = (fabsf(a0.w - b0.w) + fabsf(a1.w - b1.w)) + fabsf(a2.w - b2.w);
        *(float4*)(rb + i) = r;
        atomicAdd(&sh[__float_as_uint(r.x) >> 20], 1u);
        atomicAdd(&sh[__float_as_uint(r.y) >> 20], 1u);
        atomicAdd(&sh[__float_as_uint(r.z) >> 20], 1u);
        atomicAdd(&sh[__float_as_uint(r.w) >> 20], 1u);
    }
    __syncthreads();
    for (int i = threadIdx.x; i < 4096; i += 256) {
        unsigned c = sh[i];
        if (c) atomicAdd(&g_hist1[b][i], c);
    }
}

// ---------------- K2: candidate level-1 bin (rank HARD_IND, descending) -----------
__global__ void __launch_bounds__(1024) k_sel1() {
    int b = blockIdx.x, tid = threadIdx.x, lane = tid & 31, w = tid >> 5;
    __shared__ unsigned sh[4096];
    for (int i = tid; i < 4096; i += 1024) {
        sh[i] = g_hist1[b][i];
        g_hist1[b][i] = 0;                    // reset for next run (same-thread RAW)
    }
    __syncthreads();
    unsigned v = sh[4 * tid] + sh[4 * tid + 1] + sh[4 * tid + 2] + sh[4 * tid + 3];
    unsigned s = v;
    for (int o = 1; o < 32; o <<= 1) {
        unsigned t = __shfl_down_sync(0xffffffffu, s, o);
        if (lane + o < 32) s += t;
    }
    __shared__ unsigned wtot[32];
    if (!lane) wtot[w] = s;
    __syncthreads();
    unsigned above = 0;
    for (int u = w + 1; u < 32; ++u) above += wtot[u];
    unsigned suffExcl = above + s - v;
    if (suffExcl <= HARD_IND && HARD_IND < suffExcl + v) {
        unsigned cum = suffExcl;
        for (int j = 3; j >= 0; --j) {
            unsigned c = sh[4 * tid + j];
            if (cum + c > HARD_IND) { g_cand[b] = 4 * tid + j; g_above[b] = cum; break; }
            cum += c;
        }
    }
}

// ---------------- K3: total sum + hard-high sum + block-local compaction ----------
__global__ void __launch_bounds__(256) k_refine() {
    const int blocksPerBatch = NPIX / 4096;
    int b   = blockIdx.x / blocksPerBatch;
    int blk = blockIdx.x % blocksPerBatch;
    unsigned cand = (unsigned)g_cand[b];
    const float* rb = g_res + (size_t)b * NPIX;
    int pix0 = blk * 4096;
    int lane = threadIdx.x & 31;

    __shared__ float sbuf[BCAP];
    __shared__ unsigned scnt, sbase;
    __shared__ double whigh[8], wall[8];
    if (threadIdx.x == 0) scnt = 0;
    __syncthreads();

    float fh = 0.0f, fs = 0.0f;
#pragma unroll
    for (int it = 0; it < 4; ++it) {
        int i = pix0 + it * 1024 + threadIdx.x * 4;
        float4 r = *(const float4*)(rb + i);
        float vv[4] = {r.x, r.y, r.z, r.w};
#pragma unroll
        for (int k = 0; k < 4; ++k) {
            float v = vv[k];
            fs += v;
            unsigned bin = __float_as_uint(v) >> 20;
            if (bin > cand) fh += v;
            else if (bin == cand) {
                unsigned idx = atomicAdd(&scnt, 1u);
                if (idx < BCAP) sbuf[idx] = v;
            }
        }
    }
    for (int o = 16; o; o >>= 1) {
        fh += __shfl_down_sync(0xffffffffu, fh, o);
        fs += __shfl_down_sync(0xffffffffu, fs, o);
    }
    int w = threadIdx.x >> 5;
    if (!lane) { whigh[w] = (double)fh; wall[w] = (double)fs; }
    __syncthreads();
    if (threadIdx.x == 0) {
        double sh2 = 0.0, sa = 0.0;
        for (int i = 0; i < 8; ++i) { sh2 += whigh[i]; sa += wall[i]; }
        atomicAdd(&g_hardHigh[b], sh2);
        atomicAdd(&g_sumAll[b], sa);
        unsigned c = scnt; if (c > BCAP) c = BCAP;
        sbase = atomicAdd(&g_cmpCnt[b], c);   // one global atomic per block
        scnt = c;
    }
    __syncthreads();
    float* cb = g_cmp[b];
    unsigned c = scnt, base = sbase;
    for (unsigned i = threadIdx.x; i < c; i += 256) {
        unsigned pos = base + i;
        if (pos < CAP) cb[pos] = sbuf[i];
    }
}

// ---------------- helper: count strictly above tid (descending suffix) ------------
__device__ __forceinline__ unsigned suff_excl(unsigned v, int tid, unsigned* wtot) {
    int lane = tid & 31, w = tid >> 5;
    unsigned s = v;
    for (int o = 1; o < 32; o <<= 1) {
        unsigned t = __shfl_down_sync(0xffffffffu, s, o);
        if (lane + o < 32) s += t;
    }
    __syncthreads();
    if (!lane) wtot[w] = s;
    __syncthreads();
    unsigned above = 0;
    for (int u = w + 1; u < 32; ++u) above += wtot[u];
    return above + s - v;
}

// ---------------- K4: exact threshold + per-batch result (1 block / batch) --------
__global__ void __launch_bounds__(1024) k_final() {
    int b = blockIdx.x, tid = threadIdx.x, lane = tid & 31, w = tid >> 5;
    __shared__ unsigned cnt1[1024];
    __shared__ float    sum1[1024];
    __shared__ unsigned wtot[32];
    __shared__ double   wshd[32];
    __shared__ int sC2, sJ;
    __shared__ unsigned sRin2;
    __shared__ double sSumAbove;

    cnt1[tid] = 0; sum1[tid] = 0.0f;
    unsigned n = g_cmpCnt[b]; if (n > CAP) n = CAP;
    const float* buf = g_cmp[b];
    __syncthreads();
    if (tid == 0) g_cmpCnt[b] = 0;            // reset after all threads read n

    // pass A: bits 10..19 — count + fp32 value sum
    for (unsigned i = tid; i < n; i += 1024) {
        float v = buf[i];
        unsigned sb = (__float_as_uint(v) >> 10) & 1023u;
        atomicAdd(&cnt1[sb], 1u);
        atomicAdd(&sum1[sb], v);
    }
    __syncthreads();

    unsigned v = cnt1[tid];
    unsigned se = suff_excl(v, tid, wtot);
    unsigned rin = HARD_IND - g_above[b];
    if (se <= rin && rin < se + v) { sC2 = tid; sRin2 = rin - se; }
    __syncthreads();
    int c2 = sC2;

    double sa = (tid > c2) ? (double)sum1[tid] : 0.0;
    for (int o = 16; o; o >>= 1) sa += __shfl_down_sync(0xffffffffu, sa, o);
    if (!lane) wshd[w] = sa;
    __syncthreads();
    if (tid == 0) {
        double s = 0.0;
        for (int i = 0; i < 32; ++i) s += wshd[i];
        sSumAbove = s;
    }
    __syncthreads();

    // pass B: bits 0..9 counts within sub-bin c2
    cnt1[tid] = 0;
    __syncthreads();
    for (unsigned i = tid; i < n; i += 1024) {
        unsigned bits = __float_as_uint(buf[i]);
        if (((bits >> 10) & 1023u) == (unsigned)c2)
            atomicAdd(&cnt1[bits & 1023u], 1u);
    }
    __syncthreads();

    v = cnt1[tid];
    se = suff_excl(v, tid, wtot);
    unsigned rin2 = sRin2;
    if (se <= rin2 && rin2 < se + v) sJ = tid;
    __syncthreads();
    int jst = sJ;

    unsigned baseb = ((unsigned)g_cand[b] << 20) | ((unsigned)c2 << 10);
    double pv = (tid > jst)
        ? (double)cnt1[tid] * (double)__uint_as_float(baseb | (unsigned)tid) : 0.0;
    for (int o = 16; o; o >>= 1) pv += __shfl_down_sync(0xffffffffu, pv, o);
    if (!lane) wshd[w] = pv;
    __syncthreads();
    if (tid == 0) {
        double s = 0.0;
        for (int i = 0; i < 32; ++i) s += wshd[i];
        double hardSum = g_hardHigh[b] + sSumAbove + s;   // exact sum of res > thre
        double result  = hardSum + PSOFT * (g_sumAll[b] - hardSum);
        atomicAdd(&g_total, result);
        g_hardHigh[b] = 0.0;                  // reset for next run
        g_sumAll[b]  = 0.0;
    }
}

// ---------------- K5: final scalar + reset g_total ----------------
__global__ void k_out(float* out) {
    out[0] = (float)(g_total / TOTAL_ELEMS);
    g_total = 0.0;
}

extern "C" void kernel_launch(void* const* d_in, const int* in_sizes, int n_in,
                              void* d_out, int out_size) {
    const float* x = (const float*)d_in[0];
    const float* y = (const float*)d_in[1];
    float* out = (float*)d_out;
    k_res   <<<2048, 256>>>(x, y);
    k_sel1  <<<BATCH, 1024>>>();
    k_refine<<<2048, 256>>>();
    k_final <<<BATCH, 1024>>>();
    k_out   <<<1, 1>>>(out);
}

// round 7
// speedup vs baseline: 4.1534x; 1.0442x over previous
#include <cuda_runtime.h>
#include <cstdint>

#define BATCH 8
#define NPIX (1 << 20)
#define HARD_IND 524288u
#define PSOFT (104857.0 / 1048576.0)
#define TOTAL_ELEMS 25165824.0
#define CAP (1u << 18)          // global compact buffer per batch (expect ~33-70K used)
#define BCAP 512                // per-block smem compact capacity

// ---------------- scratch (static device memory; zero-initialized at load) -------
// INVARIANT: every consumer resets its cross-run accumulator after use.
__device__ float    g_res[BATCH * NPIX];      // 32 MB (fully rewritten each run)
__device__ unsigned g_hist1[BATCH][4096];     // zeroed by k_sel1 after reading
__device__ float    g_cmp[BATCH][CAP];        // data region bounded by g_cmpCnt
__device__ unsigned g_cmpCnt[BATCH];          // zeroed by k_final after reading
__device__ double   g_sumAll[BATCH];          // zeroed by k_final after reading
__device__ double   g_hardHigh[BATCH];        // zeroed by k_final after reading
__device__ int      g_cand[BATCH];
__device__ unsigned g_above[BATCH];
__device__ double   g_total;                  // zeroed by k_out after reading

// ---------------- K1: res = sum_c |x-y| + level-1 histogram ----------------------
__global__ void __launch_bounds__(256) k_res(const float* __restrict__ x,
                                             const float* __restrict__ y) {
    __shared__ unsigned sh[4096];
    for (int i = threadIdx.x; i < 4096; i += 256) sh[i] = 0;
    __syncthreads();

    const int blocksPerBatch = NPIX / 4096;   // 256
    int b   = blockIdx.x / blocksPerBatch;
    int blk = blockIdx.x % blocksPerBatch;
    const float* xb = x + (size_t)b * 3 * NPIX;
    const float* yb = y + (size_t)b * 3 * NPIX;
    float* rb = g_res + (size_t)b * NPIX;
    int pix0 = blk * 4096;

#pragma unroll
    for (int it = 0; it < 4; ++it) {
        int i = pix0 + it * 1024 + threadIdx.x * 4;
        float4 a0 = *(const float4*)(xb + i);
        float4 b0 = *(const float4*)(yb + i);
        float4 a1 = *(const float4*)(xb + NPIX + i);
        float4 b1 = *(const float4*)(yb + NPIX + i);
        float4 a2 = *(const float4*)(xb + 2 * NPIX + i);
        float4 b2 = *(const float4*)(yb + 2 * NPIX + i);
        float4 r;
        r.x = (fabsf(a0.x - b0.x) + fabsf(a1.x - b1.x)) + fabsf(a2.x - b2.x);
        r.y = (fabsf(a0.y - b0.y) + fabsf(a1.y - b1.y)) + fabsf(a2.y - b2.y);
        r.z = (fabsf(a0.z - b0.z) + fabsf(a1.z - b1.z)) + fabsf(a2.z - b2.z);
        r.w = (fabsf(a0.w - b0.w) + fabsf(a1.w - b1.w)) + fabsf(a2.w - b2.w);
        *(float4*)(rb + i) = r;
        atomicAdd(&sh[__float_as_uint(r.x) >> 20], 1u);
        atomicAdd(&sh[__float_as_uint(r.y) >> 20], 1u);
        atomicAdd(&sh[__float_as_uint(r.z) >> 20], 1u);
        atomicAdd(&sh[__float_as_uint(r.w) >> 20], 1u);
    }
    __syncthreads();
    for (int i = threadIdx.x; i < 4096; i += 256) {
        unsigned c = sh[i];
        if (c) atomicAdd(&g_hist1[b][i], c);
    }
}

// ---------------- K2: candidate level-1 bin (rank HARD_IND, descending) -----------
__global__ void __launch_bounds__(1024) k_sel1() {
    int b = blockIdx.x, tid = threadIdx.x, lane = tid & 31, w = tid >> 5;
    __shared__ unsigned sh[4096];
    for (int i = tid; i < 4096; i += 1024) {
        sh[i] = g_hist1[b][i];
        g_hist1[b][i] = 0;                    // reset for next run
    }
    __syncthreads();
    unsigned v = sh[4 * tid] + sh[4 * tid + 1] + sh[4 * tid + 2] + sh[4 * tid + 3];
    unsigned s = v;
    for (int o = 1; o < 32; o <<= 1) {
        unsigned t = __shfl_down_sync(0xffffffffu, s, o);
        if (lane + o < 32) s += t;
    }
    __shared__ unsigned wtot[32];
    if (!lane) wtot[w] = s;
    __syncthreads();
    unsigned above = 0;
    for (int u = w + 1; u < 32; ++u) above += wtot[u];
    unsigned suffExcl = above + s - v;
    if (suffExcl <= HARD_IND && HARD_IND < suffExcl + v) {
        unsigned cum = suffExcl;
        for (int j = 3; j >= 0; --j) {
            unsigned c = sh[4 * tid + j];
            if (cum + c > HARD_IND) { g_cand[b] = 4 * tid + j; g_above[b] = cum; break; }
            cum += c;
        }
    }
}

// ---------------- K3: total sum + hard-high sum + block-local compaction ----------
__global__ void __launch_bounds__(256) k_refine() {
    const int blocksPerBatch = NPIX / 4096;
    int b   = blockIdx.x / blocksPerBatch;
    int blk = blockIdx.x % blocksPerBatch;
    unsigned cand = (unsigned)g_cand[b];
    const float* rb = g_res + (size_t)b * NPIX;
    int pix0 = blk * 4096;
    int lane = threadIdx.x & 31;

    __shared__ float sbuf[BCAP];
    __shared__ unsigned scnt, sbase;
    __shared__ double whigh[8], wall[8];
    if (threadIdx.x == 0) scnt = 0;
    __syncthreads();

    float fh = 0.0f, fs = 0.0f;
#pragma unroll
    for (int it = 0; it < 4; ++it) {
        int i = pix0 + it * 1024 + threadIdx.x * 4;
        float4 r = *(const float4*)(rb + i);
        float vv[4] = {r.x, r.y, r.z, r.w};
#pragma unroll
        for (int k = 0; k < 4; ++k) {
            float v = vv[k];
            fs += v;
            unsigned bin = __float_as_uint(v) >> 20;
            if (bin > cand) fh += v;
            else if (bin == cand) {
                unsigned idx = atomicAdd(&scnt, 1u);
                if (idx < BCAP) sbuf[idx] = v;
            }
        }
    }
    for (int o = 16; o; o >>= 1) {
        fh += __shfl_down_sync(0xffffffffu, fh, o);
        fs += __shfl_down_sync(0xffffffffu, fs, o);
    }
    int w = threadIdx.x >> 5;
    if (!lane) { whigh[w] = (double)fh; wall[w] = (double)fs; }
    __syncthreads();
    if (threadIdx.x == 0) {
        double sh2 = 0.0, sa = 0.0;
        for (int i = 0; i < 8; ++i) { sh2 += whigh[i]; sa += wall[i]; }
        atomicAdd(&g_hardHigh[b], sh2);
        atomicAdd(&g_sumAll[b], sa);
        unsigned c = scnt; if (c > BCAP) c = BCAP;
        sbase = atomicAdd(&g_cmpCnt[b], c);   // one global atomic per block
        scnt = c;
    }
    __syncthreads();
    float* cb = g_cmp[b];
    unsigned c = scnt, base = sbase;
    for (unsigned i = threadIdx.x; i < c; i += 256) {
        unsigned pos = base + i;
        if (pos < CAP) cb[pos] = sbuf[i];
    }
}

// ---------------- helper: count strictly above tid (descending suffix) ------------
__device__ __forceinline__ unsigned suff_excl(unsigned v, int tid, unsigned* wtot) {
    int lane = tid & 31, w = tid >> 5;
    unsigned s = v;
    for (int o = 1; o < 32; o <<= 1) {
        unsigned t = __shfl_down_sync(0xffffffffu, s, o);
        if (lane + o < 32) s += t;
    }
    __syncthreads();
    if (!lane) wtot[w] = s;
    __syncthreads();
    unsigned above = 0;
    for (int u = w + 1; u < 32; ++u) above += wtot[u];
    return above + s - v;
}

// ---------------- K4: exact threshold + per-batch result (1 block / batch) --------
// Both scan passes use float4 loads batched 4-deep (MLP~4 LDG.128) to kill the
// exposed L2 latency that dominated R5 (55us at MLP=1).
__global__ void __launch_bounds__(1024) k_final() {
    int b = blockIdx.x, tid = threadIdx.x, lane = tid & 31, w = tid >> 5;
    __shared__ unsigned cnt1[1024];
    __shared__ float    sum1[1024];
    __shared__ unsigned wtot[32];
    __shared__ double   wshd[32];
    __shared__ int sC2, sJ;
    __shared__ unsigned sRin2;
    __shared__ double sSumAbove;

    cnt1[tid] = 0; sum1[tid] = 0.0f;
    unsigned n = g_cmpCnt[b]; if (n > CAP) n = CAP;
    const float*  buf  = g_cmp[b];
    const float4* buf4 = reinterpret_cast<const float4*>(buf);
    unsigned n4 = n >> 2;
    __syncthreads();
    if (tid == 0) g_cmpCnt[b] = 0;            // reset after all threads read n

    // ---- pass A: bits 10..19 — count + fp32 value sum ----
    {
        unsigned i = tid;
        for (; i + 3u * 1024u < n4; i += 4u * 1024u) {
            float4 q0 = buf4[i];
            float4 q1 = buf4[i + 1024u];
            float4 q2 = buf4[i + 2048u];
            float4 q3 = buf4[i + 3072u];
            float vals[16] = {q0.x,q0.y,q0.z,q0.w, q1.x,q1.y,q1.z,q1.w,
                              q2.x,q2.y,q2.z,q2.w, q3.x,q3.y,q3.z,q3.w};
#pragma unroll
            for (int k = 0; k < 16; ++k) {
                unsigned sb = (__float_as_uint(vals[k]) >> 10) & 1023u;
                atomicAdd(&cnt1[sb], 1u);
                atomicAdd(&sum1[sb], vals[k]);
            }
        }
        for (; i < n4; i += 1024u) {
            float4 q = buf4[i];
            float vals[4] = {q.x, q.y, q.z, q.w};
#pragma unroll
            for (int k = 0; k < 4; ++k) {
                unsigned sb = (__float_as_uint(vals[k]) >> 10) & 1023u;
                atomicAdd(&cnt1[sb], 1u);
                atomicAdd(&sum1[sb], vals[k]);
            }
        }
        for (unsigned j = (n4 << 2) + tid; j < n; j += 1024u) {
            float v2 = buf[j];
            unsigned sb = (__float_as_uint(v2) >> 10) & 1023u;
            atomicAdd(&cnt1[sb], 1u);
            atomicAdd(&sum1[sb], v2);
        }
    }
    __syncthreads();

    unsigned v = cnt1[tid];
    unsigned se = suff_excl(v, tid, wtot);
    unsigned rin = HARD_IND - g_above[b];
    if (se <= rin && rin < se + v) { sC2 = tid; sRin2 = rin - se; }
    __syncthreads();
    int c2 = sC2;

    double sa = (tid > c2) ? (double)sum1[tid] : 0.0;
    for (int o = 16; o; o >>= 1) sa += __shfl_down_sync(0xffffffffu, sa, o);
    if (!lane) wshd[w] = sa;
    __syncthreads();
    if (tid == 0) {
        double s = 0.0;
        for (int i = 0; i < 32; ++i) s += wshd[i];
        sSumAbove = s;
    }
    __syncthreads();

    // ---- pass B: bits 0..9 counts within sub-bin c2 ----
    cnt1[tid] = 0;
    __syncthreads();
    {
        unsigned uc2 = (unsigned)c2;
        unsigned i = tid;
        for (; i + 3u * 1024u < n4; i += 4u * 1024u) {
            float4 q0 = buf4[i];
            float4 q1 = buf4[i + 1024u];
            float4 q2 = buf4[i + 2048u];
            float4 q3 = buf4[i + 3072u];
            float vals[16] = {q0.x,q0.y,q0.z,q0.w, q1.x,q1.y,q1.z,q1.w,
                              q2.x,q2.y,q2.z,q2.w, q3.x,q3.y,q3.z,q3.w};
#pragma unroll
            for (int k = 0; k < 16; ++k) {
                unsigned bits = __float_as_uint(vals[k]);
                if (((bits >> 10) & 1023u) == uc2) atomicAdd(&cnt1[bits & 1023u], 1u);
            }
        }
        for (; i < n4; i += 1024u) {
            float4 q = buf4[i];
            float vals[4] = {q.x, q.y, q.z, q.w};
#pragma unroll
            for (int k = 0; k < 4; ++k) {
                unsigned bits = __float_as_uint(vals[k]);
                if (((bits >> 10) & 1023u) == uc2) atomicAdd(&cnt1[bits & 1023u], 1u);
            }
        }
        for (unsigned j = (n4 << 2) + tid; j < n; j += 1024u) {
            unsigned bits = __float_as_uint(buf[j]);
            if (((bits >> 10) & 1023u) == uc2) atomicAdd(&cnt1[bits & 1023u], 1u);
        }
    }
    __syncthreads();

    v = cnt1[tid];
    se = suff_excl(v, tid, wtot);
    unsigned rin2 = sRin2;
    if (se <= rin2 && rin2 < se + v) sJ = tid;
    __syncthreads();
    int jst = sJ;

    unsigned baseb = ((unsigned)g_cand[b] << 20) | ((unsigned)c2 << 10);
    double pv = (tid > jst)
        ? (double)cnt1[tid] * (double)__uint_as_float(baseb | (unsigned)tid) : 0.0;
    for (int o = 16; o; o >>= 1) pv += __shfl_down_sync(0xffffffffu, pv, o);
    if (!lane) wshd[w] = pv;
    __syncthreads();
    if (tid == 0) {
        double s = 0.0;
        for (int i = 0; i < 32; ++i) s += wshd[i];
        double hardSum = g_hardHigh[b] + sSumAbove + s;   // exact sum of res > thre
        double result  = hardSum + PSOFT * (g_sumAll[b] - hardSum);
        atomicAdd(&g_total, result);
        g_hardHigh[b] = 0.0;                  // reset for next run
        g_sumAll[b]  = 0.0;
    }
}

// ---------------- K5: final scalar + reset g_total ----------------
__global__ void k_out(float* out) {
    out[0] = (float)(g_total / TOTAL_ELEMS);
    g_total = 0.0;
}

extern "C" void kernel_launch(void* const* d_in, const int* in_sizes, int n_in,
                              void* d_out, int out_size) {
    const float* x = (const float*)d_in[0];
    const float* y = (const float*)d_in[1];
    float* out = (float*)d_out;
    k_res   <<<2048, 256>>>(x, y);
    k_sel1  <<<BATCH, 1024>>>();
    k_refine<<<2048, 256>>>();
    k_final <<<BATCH, 1024>>>();
    k_out   <<<1, 1>>>(out);
}

// round 8
// speedup vs baseline: 4.9520x; 1.1923x over previous
#include <cuda_runtime.h>
#include <cstdint>

#define BATCH 8
#define NPIX (1 << 20)
#define HARD_IND 524288u
#define PSOFT (104857.0 / 1048576.0)
#define TOTAL_ELEMS 25165824.0
#define CAP (1u << 18)          // global compact buffer per batch (expect ~48K used)
#define BCAP 512                // per-block smem compact capacity

// ---------------- scratch (static device memory; zero-initialized at load) -------
// INVARIANT: every consumer resets its cross-run accumulator after use.
__device__ float              g_res[BATCH * NPIX];   // 32 MB (fully rewritten)
__device__ unsigned           g_hist1[BATCH][4096];  // zeroed by k_sel1 after read
__device__ unsigned long long g_hist2[BATCH][1024];  // {cnt<<40 | sum_low10}; zeroed by k_final
__device__ float              g_cmp[BATCH][CAP];     // bounded by g_cmpCnt
__device__ unsigned           g_cmpCnt[BATCH];       // zeroed by k_final after read
__device__ double             g_sumAll[BATCH];       // zeroed by k_final after read
__device__ double             g_hardHigh[BATCH];     // zeroed by k_final after read
__device__ int                g_cand[BATCH];
__device__ unsigned           g_above[BATCH];
__device__ double             g_total;               // zeroed by k_out after read

// ---------------- K1: res = sum_c |x-y| + level-1 histogram ----------------------
__global__ void __launch_bounds__(256) k_res(const float* __restrict__ x,
                                             const float* __restrict__ y) {
    __shared__ unsigned sh[4096];
    for (int i = threadIdx.x; i < 4096; i += 256) sh[i] = 0;
    __syncthreads();

    const int blocksPerBatch = NPIX / 4096;   // 256
    int b   = blockIdx.x / blocksPerBatch;
    int blk = blockIdx.x % blocksPerBatch;
    const float* xb = x + (size_t)b * 3 * NPIX;
    const float* yb = y + (size_t)b * 3 * NPIX;
    float* rb = g_res + (size_t)b * NPIX;
    int pix0 = blk * 4096;

#pragma unroll
    for (int it = 0; it < 4; ++it) {
        int i = pix0 + it * 1024 + threadIdx.x * 4;
        float4 a0 = *(const float4*)(xb + i);
        float4 b0 = *(const float4*)(yb + i);
        float4 a1 = *(const float4*)(xb + NPIX + i);
        float4 b1 = *(const float4*)(yb + NPIX + i);
        float4 a2 = *(const float4*)(xb + 2 * NPIX + i);
        float4 b2 = *(const float4*)(yb + 2 * NPIX + i);
        float4 r;
        r.x = (fabsf(a0.x - b0.x) + fabsf(a1.x - b1.x)) + fabsf(a2.x - b2.x);
        r.y = (fabsf(a0.y - b0.y) + fabsf(a1.y - b1.y)) + fabsf(a2.y - b2.y);
        r.z = (fabsf(a0.z - b0.z) + fabsf(a1.z - b1.z)) + fabsf(a2.z - b2.z);
        r.w = (fabsf(a0.w - b0.w) + fabsf(a1.w - b1.w)) + fabsf(a2.w - b2.w);
        *(float4*)(rb + i) = r;
        atomicAdd(&sh[__float_as_uint(r.x) >> 20], 1u);
        atomicAdd(&sh[__float_as_uint(r.y) >> 20], 1u);
        atomicAdd(&sh[__float_as_uint(r.z) >> 20], 1u);
        atomicAdd(&sh[__float_as_uint(r.w) >> 20], 1u);
    }
    __syncthreads();
    for (int i = threadIdx.x; i < 4096; i += 256) {
        unsigned c = sh[i];
        if (c) atomicAdd(&g_hist1[b][i], c);
    }
}

// ---------------- K2: candidate level-1 bin (rank HARD_IND, descending) -----------
__global__ void __launch_bounds__(1024) k_sel1() {
    int b = blockIdx.x, tid = threadIdx.x, lane = tid & 31, w = tid >> 5;
    __shared__ unsigned sh[4096];
    for (int i = tid; i < 4096; i += 1024) {
        sh[i] = g_hist1[b][i];
        g_hist1[b][i] = 0;                    // reset for next run
    }
    __syncthreads();
    unsigned v = sh[4 * tid] + sh[4 * tid + 1] + sh[4 * tid + 2] + sh[4 * tid + 3];
    unsigned s = v;
    for (int o = 1; o < 32; o <<= 1) {
        unsigned t = __shfl_down_sync(0xffffffffu, s, o);
        if (lane + o < 32) s += t;
    }
    __shared__ unsigned wtot[32];
    if (!lane) wtot[w] = s;
    __syncthreads();
    unsigned above = 0;
    for (int u = w + 1; u < 32; ++u) above += wtot[u];
    unsigned suffExcl = above + s - v;
    if (suffExcl <= HARD_IND && HARD_IND < suffExcl + v) {
        unsigned cum = suffExcl;
        for (int j = 3; j >= 0; --j) {
            unsigned c = sh[4 * tid + j];
            if (cum + c > HARD_IND) { g_cand[b] = 4 * tid + j; g_above[b] = cum; break; }
            cum += c;
        }
    }
}

// ---------------- K3: sums + compaction + distributed level-2 histogram -----------
__global__ void __launch_bounds__(256) k_refine() {
    const int blocksPerBatch = NPIX / 4096;
    int b   = blockIdx.x / blocksPerBatch;
    int blk = blockIdx.x % blocksPerBatch;
    unsigned cand = (unsigned)g_cand[b];
    const float* rb = g_res + (size_t)b * NPIX;
    int pix0 = blk * 4096;
    int lane = threadIdx.x & 31;

    __shared__ float sbuf[BCAP];
    __shared__ unsigned long long sh2[1024];  // {cnt<<40 | sum_low10} per sub-bin
    __shared__ unsigned scnt, sbase;
    __shared__ double whigh[8], wall[8];
    if (threadIdx.x == 0) scnt = 0;
    for (int i = threadIdx.x; i < 1024; i += 256) sh2[i] = 0ull;
    __syncthreads();

    float fh = 0.0f, fs = 0.0f;
#pragma unroll
    for (int it = 0; it < 4; ++it) {
        int i = pix0 + it * 1024 + threadIdx.x * 4;
        float4 r = *(const float4*)(rb + i);
        float vv[4] = {r.x, r.y, r.z, r.w};
#pragma unroll
        for (int k = 0; k < 4; ++k) {
            float v = vv[k];
            fs += v;
            unsigned bits = __float_as_uint(v);
            unsigned bin = bits >> 20;
            if (bin > cand) fh += v;
            else if (bin == cand) {
                atomicAdd(&sh2[(bits >> 10) & 1023u],
                          (1ull << 40) | (unsigned long long)(bits & 1023u));
                unsigned idx = atomicAdd(&scnt, 1u);
                if (idx < BCAP) sbuf[idx] = v;
            }
        }
    }
    for (int o = 16; o; o >>= 1) {
        fh += __shfl_down_sync(0xffffffffu, fh, o);
        fs += __shfl_down_sync(0xffffffffu, fs, o);
    }
    int w = threadIdx.x >> 5;
    if (!lane) { whigh[w] = (double)fh; wall[w] = (double)fs; }
    __syncthreads();
    if (threadIdx.x == 0) {
        double sh_ = 0.0, sa = 0.0;
        for (int i = 0; i < 8; ++i) { sh_ += whigh[i]; sa += wall[i]; }
        atomicAdd(&g_hardHigh[b], sh_);
        atomicAdd(&g_sumAll[b], sa);
        unsigned c = scnt; if (c > BCAP) c = BCAP;
        sbase = atomicAdd(&g_cmpCnt[b], c);   // one global atomic per block
        scnt = c;
    }
    __syncthreads();
    float* cb = g_cmp[b];
    unsigned c = scnt, base = sbase;
    for (unsigned i = threadIdx.x; i < c; i += 256) {
        unsigned pos = base + i;
        if (pos < CAP) cb[pos] = sbuf[i];
    }
    // flush only nonzero level-2 bins (~24 per block) — spread over 1024 addrs
    for (int i = threadIdx.x; i < 1024; i += 256) {
        unsigned long long h = sh2[i];
        if (h) atomicAdd(&g_hist2[b][i], h);
    }
}

// ---------------- helper: count strictly above tid (descending suffix) ------------
__device__ __forceinline__ unsigned suff_excl(unsigned v, int tid, unsigned* wtot) {
    int lane = tid & 31, w = tid >> 5;
    unsigned s = v;
    for (int o = 1; o < 32; o <<= 1) {
        unsigned t = __shfl_down_sync(0xffffffffu, s, o);
        if (lane + o < 32) s += t;
    }
    __syncthreads();
    if (!lane) wtot[w] = s;
    __syncthreads();
    unsigned above = 0;
    for (int u = w + 1; u < 32; ++u) above += wtot[u];
    return above + s - v;
}

// ---------------- K4: exact threshold + per-batch result (1 block / batch) --------
__global__ void __launch_bounds__(1024) k_final() {
    int b = blockIdx.x, tid = threadIdx.x, lane = tid & 31, w = tid >> 5;
    __shared__ unsigned cnt1[1024];
    __shared__ unsigned wtot[32];
    __shared__ double   wshd[32];
    __shared__ int sC2, sJ;
    __shared__ unsigned sRin2;
    __shared__ double sSumAbove;

    unsigned n = g_cmpCnt[b]; if (n > CAP) n = CAP;
    const float*  buf  = g_cmp[b];
    const float4* buf4 = reinterpret_cast<const float4*>(buf);
    unsigned n4 = n >> 2;
    unsigned cand = (unsigned)g_cand[b];

    // ---- pass A replacement: read precomputed level-2 histogram (exact sums) ----
    unsigned long long h = g_hist2[b][tid];
    g_hist2[b][tid] = 0ull;                   // reset for next run (same thread)
    if (tid == 0) g_cmpCnt[b] = 0;
    unsigned cnt = (unsigned)(h >> 40);
    double sumlow = (double)(h & 0xFFFFFFFFFFull);
    unsigned bb   = (cand << 20) | ((unsigned)tid << 10);
    double base   = (double)__uint_as_float(bb);
    double ulp    = (double)__uint_as_float((cand << 20) | 1u)
                  - (double)__uint_as_float(cand << 20);   // exact
    double binsum = (double)cnt * base + sumlow * ulp;     // exact sub-bin sum

    unsigned se = suff_excl(cnt, tid, wtot);
    unsigned rin = HARD_IND - g_above[b];
    if (se <= rin && rin < se + cnt) { sC2 = tid; sRin2 = rin - se; }
    __syncthreads();
    int c2 = sC2;

    double sa = (tid > c2) ? binsum : 0.0;
    for (int o = 16; o; o >>= 1) sa += __shfl_down_sync(0xffffffffu, sa, o);
    if (!lane) wshd[w] = sa;
    __syncthreads();
    if (tid == 0) {
        double s = 0.0;
        for (int i = 0; i < 32; ++i) s += wshd[i];
        sSumAbove = s;
    }

    // ---- pass B: bits 0..9 counts within sub-bin c2 (scan compact buffer) ----
    cnt1[tid] = 0;
    __syncthreads();
    {
        unsigned uc2 = (unsigned)c2;
        unsigned i = tid;
        for (; i + 3u * 1024u < n4; i += 4u * 1024u) {
            float4 q0 = buf4[i];
            float4 q1 = buf4[i + 1024u];
            float4 q2 = buf4[i + 2048u];
            float4 q3 = buf4[i + 3072u];
            float vals[16] = {q0.x,q0.y,q0.z,q0.w, q1.x,q1.y,q1.z,q1.w,
                              q2.x,q2.y,q2.z,q2.w, q3.x,q3.y,q3.z,q3.w};
#pragma unroll
            for (int k = 0; k < 16; ++k) {
                unsigned bits = __float_as_uint(vals[k]);
                if (((bits >> 10) & 1023u) == uc2) atomicAdd(&cnt1[bits & 1023u], 1u);
            }
        }
        for (; i < n4; i += 1024u) {
            float4 q = buf4[i];
            float vals[4] = {q.x, q.y, q.z, q.w};
#pragma unroll
            for (int k = 0; k < 4; ++k) {
                unsigned bits = __float_as_uint(vals[k]);
                if (((bits >> 10) & 1023u) == uc2) atomicAdd(&cnt1[bits & 1023u], 1u);
            }
        }
        for (unsigned j = (n4 << 2) + tid; j < n; j += 1024u) {
            unsigned bits = __float_as_uint(buf[j]);
            if (((bits >> 10) & 1023u) == uc2) atomicAdd(&cnt1[bits & 1023u], 1u);
        }
    }
    __syncthreads();

    unsigned v = cnt1[tid];
    se = suff_excl(v, tid, wtot);
    unsigned rin2 = sRin2;
    if (se <= rin2 && rin2 < se + v) sJ = tid;
    __syncthreads();
    int jst = sJ;

    unsigned baseb = (cand << 20) | ((unsigned)c2 << 10);
    double pv = (tid > jst)
        ? (double)cnt1[tid] * (double)__uint_as_float(baseb | (unsigned)tid) : 0.0;
    for (int o = 16; o; o >>= 1) pv += __shfl_down_sync(0xffffffffu, pv, o);
    if (!lane) wshd[w] = pv;
    __syncthreads();
    if (tid == 0) {
        double s = 0.0;
        for (int i = 0; i < 32; ++i) s += wshd[i];
        double hardSum = g_hardHigh[b] + sSumAbove + s;   // exact sum of res > thre
        double result  = hardSum + PSOFT * (g_sumAll[b] - hardSum);
        atomicAdd(&g_total, result);
        g_hardHigh[b] = 0.0;                  // reset for next run
        g_sumAll[b]  = 0.0;
    }
}

// ---------------- K5: final scalar + reset g_total ----------------
__global__ void k_out(float* out) {
    out[0] = (float)(g_total / TOTAL_ELEMS);
    g_total = 0.0;
}

extern "C" void kernel_launch(void* const* d_in, const int* in_sizes, int n_in,
                              void* d_out, int out_size) {
    const float* x = (const float*)d_in[0];
    const float* y = (const float*)d_in[1];
    float* out = (float*)d_out;
    k_res   <<<2048, 256>>>(x, y);
    k_sel1  <<<BATCH, 1024>>>();
    k_refine<<<2048, 256>>>();
    k_final <<<BATCH, 1024>>>();
    k_out   <<<1, 1>>>(out);
}

// round 9
// speedup vs baseline: 5.7847x; 1.1682x over previous
#include <cuda_runtime.h>
#include <cstdint>

#define BATCH 8
#define NPIX (1 << 20)
#define HARD_IND 524288u
#define PSOFT (104857.0 / 1048576.0)
#define TOTAL_ELEMS 25165824.0

// ---------------- scratch (static device memory; zero-initialized at load) -------
// INVARIANT: every consumer resets its cross-run accumulator after use.
__device__ float              g_res[BATCH * NPIX];   // 32 MB (fully rewritten)
__device__ unsigned           g_hist1[BATCH][4096];  // zeroed by k_sel1 after read
__device__ unsigned long long g_hist2[BATCH][1024];  // {cnt<<40 | sum_low10}; zeroed by k_final
__device__ double             g_sumAll[BATCH];       // zeroed by k_final after read
__device__ double             g_hardHigh[BATCH];     // zeroed by k_final after read
__device__ int                g_cand[BATCH];
__device__ unsigned           g_above[BATCH];
__device__ double             g_total;               // zeroed by k_out after read

// ---------------- K1: res = sum_c |x-y| + level-1 histogram ----------------------
__global__ void __launch_bounds__(256) k_res(const float* __restrict__ x,
                                             const float* __restrict__ y) {
    __shared__ unsigned sh[4096];
    for (int i = threadIdx.x; i < 4096; i += 256) sh[i] = 0;
    __syncthreads();

    const int blocksPerBatch = NPIX / 4096;   // 256
    int b   = blockIdx.x / blocksPerBatch;
    int blk = blockIdx.x % blocksPerBatch;
    const float* xb = x + (size_t)b * 3 * NPIX;
    const float* yb = y + (size_t)b * 3 * NPIX;
    float* rb = g_res + (size_t)b * NPIX;
    int pix0 = blk * 4096;

#pragma unroll
    for (int it = 0; it < 4; ++it) {
        int i = pix0 + it * 1024 + threadIdx.x * 4;
        float4 a0 = *(const float4*)(xb + i);
        float4 b0 = *(const float4*)(yb + i);
        float4 a1 = *(const float4*)(xb + NPIX + i);
        float4 b1 = *(const float4*)(yb + NPIX + i);
        float4 a2 = *(const float4*)(xb + 2 * NPIX + i);
        float4 b2 = *(const float4*)(yb + 2 * NPIX + i);
        float4 r;
        r.x = (fabsf(a0.x - b0.x) + fabsf(a1.x - b1.x)) + fabsf(a2.x - b2.x);
        r.y = (fabsf(a0.y - b0.y) + fabsf(a1.y - b1.y)) + fabsf(a2.y - b2.y);
        r.z = (fabsf(a0.z - b0.z) + fabsf(a1.z - b1.z)) + fabsf(a2.z - b2.z);
        r.w = (fabsf(a0.w - b0.w) + fabsf(a1.w - b1.w)) + fabsf(a2.w - b2.w);
        *(float4*)(rb + i) = r;
        atomicAdd(&sh[__float_as_uint(r.x) >> 20], 1u);
        atomicAdd(&sh[__float_as_uint(r.y) >> 20], 1u);
        atomicAdd(&sh[__float_as_uint(r.z) >> 20], 1u);
        atomicAdd(&sh[__float_as_uint(r.w) >> 20], 1u);
    }
    __syncthreads();
    for (int i = threadIdx.x; i < 4096; i += 256) {
        unsigned c = sh[i];
        if (c) atomicAdd(&g_hist1[b][i], c);
    }
}

// ---------------- K2: candidate level-1 bin (rank HARD_IND, descending) -----------
__global__ void __launch_bounds__(1024) k_sel1() {
    int b = blockIdx.x, tid = threadIdx.x, lane = tid & 31, w = tid >> 5;
    __shared__ unsigned sh[4096];
    for (int i = tid; i < 4096; i += 1024) {
        sh[i] = g_hist1[b][i];
        g_hist1[b][i] = 0;                    // reset for next run
    }
    __syncthreads();
    unsigned v = sh[4 * tid] + sh[4 * tid + 1] + sh[4 * tid + 2] + sh[4 * tid + 3];
    unsigned s = v;
    for (int o = 1; o < 32; o <<= 1) {
        unsigned t = __shfl_down_sync(0xffffffffu, s, o);
        if (lane + o < 32) s += t;
    }
    __shared__ unsigned wtot[32];
    if (!lane) wtot[w] = s;
    __syncthreads();
    unsigned above = 0;
    for (int u = w + 1; u < 32; ++u) above += wtot[u];
    unsigned suffExcl = above + s - v;
    if (suffExcl <= HARD_IND && HARD_IND < suffExcl + v) {
        unsigned cum = suffExcl;
        for (int j = 3; j >= 0; --j) {
            unsigned c = sh[4 * tid + j];
            if (cum + c > HARD_IND) { g_cand[b] = 4 * tid + j; g_above[b] = cum; break; }
            cum += c;
        }
    }
}

// ---------------- K3: sums + distributed packed level-2 histogram -----------------
__global__ void __launch_bounds__(256) k_refine() {
    const int blocksPerBatch = NPIX / 4096;
    int b   = blockIdx.x / blocksPerBatch;
    int blk = blockIdx.x % blocksPerBatch;
    unsigned cand = (unsigned)g_cand[b];
    const float* rb = g_res + (size_t)b * NPIX;
    int pix0 = blk * 4096;
    int lane = threadIdx.x & 31;

    __shared__ unsigned long long sh2[1024];  // {cnt<<40 | sum_low10} per sub-bin
    __shared__ double whigh[8], wall[8];
    for (int i = threadIdx.x; i < 1024; i += 256) sh2[i] = 0ull;
    __syncthreads();

    float fh = 0.0f, fs = 0.0f;
#pragma unroll
    for (int it = 0; it < 4; ++it) {
        int i = pix0 + it * 1024 + threadIdx.x * 4;
        float4 r = *(const float4*)(rb + i);
        float vv[4] = {r.x, r.y, r.z, r.w};
#pragma unroll
        for (int k = 0; k < 4; ++k) {
            float v = vv[k];
            fs += v;
            unsigned bits = __float_as_uint(v);
            unsigned bin = bits >> 20;
            if (bin > cand) fh += v;
            else if (bin == cand)
                atomicAdd(&sh2[(bits >> 10) & 1023u],
                          (1ull << 40) | (unsigned long long)(bits & 1023u));
        }
    }
    for (int o = 16; o; o >>= 1) {
        fh += __shfl_down_sync(0xffffffffu, fh, o);
        fs += __shfl_down_sync(0xffffffffu, fs, o);
    }
    int w = threadIdx.x >> 5;
    if (!lane) { whigh[w] = (double)fh; wall[w] = (double)fs; }
    __syncthreads();
    if (threadIdx.x == 0) {
        double sh_ = 0.0, sa = 0.0;
        for (int i = 0; i < 8; ++i) { sh_ += whigh[i]; sa += wall[i]; }
        atomicAdd(&g_hardHigh[b], sh_);
        atomicAdd(&g_sumAll[b], sa);
    }
    __syncthreads();
    // flush only nonzero level-2 bins (~25 per block) — spread over 1024 addrs
    for (int i = threadIdx.x; i < 1024; i += 256) {
        unsigned long long h = sh2[i];
        if (h) atomicAdd(&g_hist2[b][i], h);
    }
}

// ---------------- helper: count strictly above tid (descending suffix) ------------
__device__ __forceinline__ unsigned suff_excl(unsigned v, int tid, unsigned* wtot) {
    int lane = tid & 31, w = tid >> 5;
    unsigned s = v;
    for (int o = 1; o < 32; o <<= 1) {
        unsigned t = __shfl_down_sync(0xffffffffu, s, o);
        if (lane + o < 32) s += t;
    }
    __syncthreads();
    if (!lane) wtot[w] = s;
    __syncthreads();
    unsigned above = 0;
    for (int u = w + 1; u < 32; ++u) above += wtot[u];
    return above + s - v;
}

// ---------------- K4: per-batch result from packed histogram (no memory scan) -----
// Within-sub-bin rank resolved by the sub-bin MEAN (exact cnt + exact low-bit sum);
// sub-bin width ~2.4e-4 x ~47 elems -> |error| <= 0.011 on a ~2.4e6 sum: rel ~5e-9.
__global__ void __launch_bounds__(1024) k_final() {
    int b = blockIdx.x, tid = threadIdx.x, lane = tid & 31, w = tid >> 5;
    __shared__ unsigned wtot[32];
    __shared__ double   wshd[32];
    __shared__ int sC2;
    __shared__ unsigned sRin2;

    unsigned cand = (unsigned)g_cand[b];

    unsigned long long h = g_hist2[b][tid];
    g_hist2[b][tid] = 0ull;                   // reset for next run (same thread)
    unsigned cnt   = (unsigned)(h >> 40);
    double sumlow  = (double)(h & 0xFFFFFFFFFFull);
    double base    = (double)__uint_as_float((cand << 20) | ((unsigned)tid << 10));
    double ulp     = (double)__uint_as_float((cand << 20) | 1u)
                   - (double)__uint_as_float(cand << 20);   // exact
    double binsum  = (double)cnt * base + sumlow * ulp;     // exact sub-bin sum

    unsigned se  = suff_excl(cnt, tid, wtot);
    unsigned rin = HARD_IND - g_above[b];
    if (se <= rin && rin < se + cnt) { sC2 = tid; sRin2 = rin - se; }
    __syncthreads();
    int c2 = sC2;

    // keep my own cnt/binsum visible for the c2 thread via shared
    __shared__ double sC2sum; __shared__ unsigned sC2cnt;
    if (tid == c2) { sC2sum = binsum; sC2cnt = cnt; }

    double sa = (tid > c2) ? binsum : 0.0;
    for (int o = 16; o; o >>= 1) sa += __shfl_down_sync(0xffffffffu, sa, o);
    if (!lane) wshd[w] = sa;
    __syncthreads();
    if (tid == 0) {
        double s = 0.0;
        for (int i = 0; i < 32; ++i) s += wshd[i];
        double meanC2 = sC2sum / (double)sC2cnt;
        double within = (double)sRin2 * meanC2;   // top-rin2 elems ~ sub-bin mean
        double hardSum = g_hardHigh[b] + s + within;
        double result  = hardSum + PSOFT * (g_sumAll[b] - hardSum);
        atomicAdd(&g_total, result);
        g_hardHigh[b] = 0.0;                  // reset for next run
        g_sumAll[b]  = 0.0;
    }
}

// ---------------- K5: final scalar + reset g_total ----------------
__global__ void k_out(float* out) {
    out[0] = (float)(g_total / TOTAL_ELEMS);
    g_total = 0.0;
}

extern "C" void kernel_launch(void* const* d_in, const int* in_sizes, int n_in,
                              void* d_out, int out_size) {
    const float* x = (const float*)d_in[0];
    const float* y = (const float*)d_in[1];
    float* out = (float*)d_out;
    k_res   <<<2048, 256>>>(x, y);
    k_sel1  <<<BATCH, 1024>>>();
    k_refine<<<2048, 256>>>();
    k_final <<<BATCH, 1024>>>();
    k_out   <<<1, 1>>>(out);
}